// round 14
// baseline (speedup 1.0000x reference)
#include <cuda_runtime.h>
#include <cstdint>

// FeaturesLoss hybrid: per-SM 2 CTAs run fp8 mma.sync (legacy tensor pipe,
// ~340 MAC/cyc/SM hard issue ceiling) + 1 CTA runs int8 dp4a on the ALU pipe.
// Persistent CTAs pull 128x64 tiles from a global atomic queue.

#define BM 128
#define BN 64
#define BK 128
#define NTHREADS 256
#define MAXN 4096
#define MAXD 512
#define SSTRB 144
#define NSTG 2

#define STAGE_A_BYTES (BM * SSTRB)            // 18432
#define STAGE_B_BYTES (BN * SSTRB)            // 9216
#define SM_A 0
#define SM_B (NSTG * STAGE_A_BYTES)           // 36864
#define SM_SQA (SM_B + NSTG * STAGE_B_BYTES)  // 55296
#define SM_SQB (SM_SQA + 512)
#define SM_LABA (SM_SQB + 256)
#define SM_LABB (SM_LABA + 512)
#define SM_RED (SM_LABB + 256)
#define SM_TILE (SM_RED + 96)
#define SMEM_TOTAL (SM_TILE + 32)

#define QSCALE 23.0f
#define INV_Q2 (1.0f / (QSCALE * QSCALE))

__device__ float g_sq[MAXN];
__device__ __align__(16) uint8_t g_Xf8[MAXN * MAXD];
__device__ __align__(16) uint8_t g_Xi8[MAXN * MAXD];
__device__ double g_sum1;
__device__ double g_sum2;
__device__ unsigned long long g_cnt;
__device__ unsigned int g_done;
__device__ unsigned int g_next;

__device__ __forceinline__ uint32_t smem_u32(const void* p) {
    uint32_t a;
    asm("{ .reg .u64 t; cvta.to.shared.u64 t, %1; cvt.u32.u64 %0, t; }"
        : "=r"(a) : "l"(p));
    return a;
}

#define CP_ASYNC16(dst_u32, src) \
    asm volatile("cp.async.cg.shared.global [%0], [%1], 16;" :: "r"(dst_u32), "l"(src))
#define CP_COMMIT() asm volatile("cp.async.commit_group;" ::: "memory")
#define CP_WAIT0()  asm volatile("cp.async.wait_group 0;" ::: "memory")

#define LDSM_X4(r0, r1, r2, r3, a)                                        \
    asm volatile("ldmatrix.sync.aligned.m8n8.x4.shared.b16 "              \
                 "{%0,%1,%2,%3}, [%4];"                                   \
                 : "=r"(r0), "=r"(r1), "=r"(r2), "=r"(r3) : "r"(a))

#define MMA16832(c, a0, a1, a2, a3, b0, b1)                               \
    asm("mma.sync.aligned.m16n8k32.row.col.f32.e4m3.e4m3.f32 "            \
        "{%0,%1,%2,%3}, {%4,%5,%6,%7}, {%8,%9}, {%0,%1,%2,%3};"           \
        : "+f"((c)[0]), "+f"((c)[1]), "+f"((c)[2]), "+f"((c)[3])          \
        : "r"(a0), "r"(a1), "r"(a2), "r"(a3), "r"(b0), "r"(b1))

__device__ __forceinline__ uint32_t pack_e4m3x4(float4 v) {
    uint16_t lo, hi;
    asm("cvt.rn.satfinite.e4m3x2.f32 %0, %1, %2;" : "=h"(lo) : "f"(v.y), "f"(v.x));
    asm("cvt.rn.satfinite.e4m3x2.f32 %0, %1, %2;" : "=h"(hi) : "f"(v.w), "f"(v.z));
    return (uint32_t)lo | ((uint32_t)hi << 16);
}
__device__ __forceinline__ int q8(float x) {
    int v = __float2int_rn(x * QSCALE);
    return max(-127, min(127, v));
}
__device__ __forceinline__ uint32_t pack_s8x4(float4 v) {
    return (uint32_t)(q8(v.x) & 0xFF) | ((uint32_t)(q8(v.y) & 0xFF) << 8) |
           ((uint32_t)(q8(v.z) & 0xFF) << 16) | ((uint32_t)(q8(v.w) & 0xFF) << 24);
}

__device__ __forceinline__ void decode_tile(int t, int ntn, int& br, int& bc) {
    int b = t, r = 0, rl = ntn;
    while (b >= rl) {
        b -= rl;
        rl -= 2;
        r++;
    }
    br = r;
    bc = 2 * r + b;
}

// ---------------------------------------------------------------------------
// Kernel A: X -> e4m3 AND s8 + exact fp32 row norms; reset accumulators/queue.
// ---------------------------------------------------------------------------
__global__ void __launch_bounds__(128) convert_kernel(const float* __restrict__ X,
                                                      int n, int d) {
    if (blockIdx.x == 0 && threadIdx.x == 0) {
        g_sum1 = 0.0;
        g_sum2 = 0.0;
        g_cnt = 0ull;
        g_done = 0u;
        g_next = 0u;
    }
    const int w = threadIdx.x >> 5, l = threadIdx.x & 31;
    const int row = blockIdx.x * 4 + w;
    if (row >= n) return;
    const float4* src = reinterpret_cast<const float4*>(X + (size_t)row * d);
    uint32_t* df = reinterpret_cast<uint32_t*>(g_Xf8 + (size_t)row * d);
    uint32_t* di = reinterpret_cast<uint32_t*>(g_Xi8 + (size_t)row * d);
    float s = 0.0f;
    if (d == 512) {
        float4 v[4];
#pragma unroll
        for (int i = 0; i < 4; i++) v[i] = src[l + 32 * i];
#pragma unroll
        for (int i = 0; i < 4; i++) {
            s = fmaf(v[i].x, v[i].x,
                     fmaf(v[i].y, v[i].y,
                          fmaf(v[i].z, v[i].z, fmaf(v[i].w, v[i].w, s))));
            df[l + 32 * i] = pack_e4m3x4(v[i]);
            di[l + 32 * i] = pack_s8x4(v[i]);
        }
    } else {
        for (int c4 = l; c4 * 4 < d; c4 += 32) {
            float4 v = src[c4];
            s = fmaf(v.x, v.x, fmaf(v.y, v.y, fmaf(v.z, v.z, fmaf(v.w, v.w, s))));
            df[c4] = pack_e4m3x4(v);
            di[c4] = pack_s8x4(v);
        }
    }
#pragma unroll
    for (int o = 16; o > 0; o >>= 1) s += __shfl_down_sync(0xffffffffu, s, o);
    if (l == 0) g_sq[row] = s;
}

// ---------------------------------------------------------------------------
// Kernel B: persistent hybrid Gram (work queue) + fused epilogue + finalize.
// ---------------------------------------------------------------------------
__global__ void __launch_bounds__(NTHREADS, 3) pair_kernel(
    const int* __restrict__ lab, const float* __restrict__ marginp,
    float* __restrict__ out, int n, int d, int ntn, int nb) {
    extern __shared__ __align__(1024) uint8_t smem[];
    const uint32_t sbase = smem_u32(smem);
    float* sqA = reinterpret_cast<float*>(smem + SM_SQA);
    float* sqB = reinterpret_cast<float*>(smem + SM_SQB);
    int* labA = reinterpret_cast<int*>(smem + SM_LABA);
    int* labB = reinterpret_cast<int*>(smem + SM_LABB);
    volatile unsigned int* smTile =
        reinterpret_cast<volatile unsigned int*>(smem + SM_TILE);

    const int tid = threadIdx.x;
    const int wid = tid >> 5, lane = tid & 31;
    const bool roleDp = (blockIdx.x % 3) == 2;  // 1 of 3 co-resident CTAs

    const int nChunks = d / BK;  // 4
    const float margin = *marginp;
    const uint8_t* __restrict__ Xsrc = roleDp ? g_Xi8 : g_Xf8;

    // Shared loader geometry (identical bytes for both roles).
    const int ldRow = tid >> 3;
    const int ldKC = (tid & 7) * 16;
    const uint32_t sOffBase = (uint32_t)ldRow * SSTRB + (uint32_t)ldKC;
    uint32_t gAbase = 0, gBbase = 0;

#define LOAD_CHUNK(cc, slot)                                                   \
    do {                                                                       \
        const uint32_t aB_ = sbase + SM_A + (uint32_t)(slot) * STAGE_A_BYTES;  \
        const uint32_t bB_ = sbase + SM_B + (uint32_t)(slot) * STAGE_B_BYTES;  \
        const uint32_t ck_ = (uint32_t)((cc) * BK);                            \
        CP_ASYNC16(aB_ + sOffBase + 0u * (32 * SSTRB),                         \
                   Xsrc + gAbase + ck_ + 0u * 32u * (uint32_t)d);              \
        CP_ASYNC16(aB_ + sOffBase + 1u * (32 * SSTRB),                         \
                   Xsrc + gAbase + ck_ + 1u * 32u * (uint32_t)d);              \
        CP_ASYNC16(aB_ + sOffBase + 2u * (32 * SSTRB),                         \
                   Xsrc + gAbase + ck_ + 2u * 32u * (uint32_t)d);              \
        CP_ASYNC16(aB_ + sOffBase + 3u * (32 * SSTRB),                         \
                   Xsrc + gAbase + ck_ + 3u * 32u * (uint32_t)d);              \
        CP_ASYNC16(bB_ + sOffBase + 0u * (32 * SSTRB),                         \
                   Xsrc + gBbase + ck_ + 0u * 32u * (uint32_t)d);              \
        CP_ASYNC16(bB_ + sOffBase + 1u * (32 * SSTRB),                         \
                   Xsrc + gBbase + ck_ + 1u * 32u * (uint32_t)d);              \
    } while (0)

    // Tensor-role fragment addressing.
    const int warpM = wid & 3, warpN = wid >> 2;
    const uint32_t laneRow = (uint32_t)(lane & 15) * SSTRB;
    const uint32_t laneK = (uint32_t)(lane >> 4) * 16;
    const uint32_t aLane = (uint32_t)(warpM * 32) * SSTRB + laneRow + laneK;
    const uint32_t bLane = (uint32_t)(warpN * 32) * SSTRB + laneRow + laneK;

    // DP4A-role thread mapping: 16x16 threads, 8x4 outputs each.
    const int tr = tid >> 4, tc = tid & 15;

    float s1 = 0.0f, s2 = 0.0f;
    unsigned int cnt = 0;

    for (;;) {
        __syncthreads();  // WAR: smTile/metadata from previous tile fully read
        if (tid == 0) *smTile = atomicAdd(&g_next, 1u);
        __syncthreads();
        const int t = (int)*smTile;
        if (t >= nb) break;

        int br, bc;
        decode_tile(t, ntn, br, bc);
        const int rowBase = br * BM, colBase = bc * BN;
        if (tid < 128) {
            sqA[tid] = g_sq[rowBase + tid];
            labA[tid] = lab[rowBase + tid];
        } else if (tid < 192) {
            int i = tid - 128;
            sqB[i] = g_sq[colBase + i];
            labB[i] = lab[colBase + i];
        }
        gAbase = (uint32_t)(rowBase + ldRow) * (uint32_t)d + (uint32_t)ldKC;
        gBbase = (uint32_t)(colBase + ldRow) * (uint32_t)d + (uint32_t)ldKC;

        LOAD_CHUNK(0, 0);
        CP_COMMIT();

        const bool straddle = (bc - 2 * br) < 2;

        if (!roleDp) {
            // ---------------- fp8 tensor path ----------------
            float acc[2][4][4];
#pragma unroll
            for (int mt = 0; mt < 2; mt++)
#pragma unroll
                for (int nt2 = 0; nt2 < 4; nt2++)
#pragma unroll
                    for (int e = 0; e < 4; e++) acc[mt][nt2][e] = 0.0f;

            for (int c = 0; c < nChunks; c++) {
                CP_WAIT0();
                __syncthreads();
                if (c + 1 < nChunks) LOAD_CHUNK(c + 1, (c + 1) & 1);
                CP_COMMIT();
                const uint32_t slot = (uint32_t)(c & 1);
                const uint32_t aBase = sbase + SM_A + slot * STAGE_A_BYTES + aLane;
                const uint32_t bBase = sbase + SM_B + slot * STAGE_B_BYTES + bLane;
#pragma unroll
                for (int ks = 0; ks < 4; ks++) {
                    uint32_t a[2][4];
#pragma unroll
                    for (int mt = 0; mt < 2; mt++)
                        LDSM_X4(a[mt][0], a[mt][1], a[mt][2], a[mt][3],
                                aBase + (uint32_t)mt * 16 * SSTRB +
                                    (uint32_t)ks * 32);
#pragma unroll
                    for (int ntp = 0; ntp < 2; ntp++) {
                        uint32_t r0, r1, r2, r3;
                        LDSM_X4(r0, r1, r2, r3,
                                bBase + (uint32_t)ntp * 16 * SSTRB +
                                    (uint32_t)ks * 32);
#pragma unroll
                        for (int mt = 0; mt < 2; mt++) {
                            MMA16832(acc[mt][2 * ntp + 0], a[mt][0], a[mt][1],
                                     a[mt][2], a[mt][3], r0, r2);
                            MMA16832(acc[mt][2 * ntp + 1], a[mt][0], a[mt][1],
                                     a[mt][2], a[mt][3], r1, r3);
                        }
                    }
                }
            }
            // Epilogue (fragment layout).
#pragma unroll
            for (int mt = 0; mt < 2; mt++) {
                const int i0 = warpM * 32 + mt * 16 + (lane >> 2);
#pragma unroll
                for (int half = 0; half < 2; half++) {
                    const int iloc = i0 + half * 8;
                    const int gi = rowBase + iloc;
                    const float sqi = sqA[iloc];
                    const int li = labA[iloc];
#pragma unroll
                    for (int nt2 = 0; nt2 < 4; nt2++) {
#pragma unroll
                        for (int e = 0; e < 2; e++) {
                            const int jloc =
                                warpN * 32 + nt2 * 8 + (lane & 3) * 2 + e;
                            const int gj = colBase + jloc;
                            float w = 2.0f;
                            if (straddle)
                                w = (gi > gj) ? 0.0f : ((gi == gj) ? 1.0f : 2.0f);
                            if (w != 0.0f) {
                                float D = sqi + sqB[jloc] -
                                          2.0f * acc[mt][nt2][half * 2 + e];
                                D = fmaxf(D, 0.0f);
                                if (li == labB[jloc]) {
                                    s1 += w * D;
                                    cnt += (unsigned int)w;
                                } else {
                                    s2 += w * fmaxf(0.0f, margin - D);
                                }
                            }
                        }
                    }
                }
            }
        } else {
            // ---------------- int8 dp4a path ----------------
            int acc[8][4];
#pragma unroll
            for (int i = 0; i < 8; i++)
#pragma unroll
                for (int j = 0; j < 4; j++) acc[i][j] = 0;

            for (int c = 0; c < nChunks; c++) {
                CP_WAIT0();
                __syncthreads();
                if (c + 1 < nChunks) LOAD_CHUNK(c + 1, (c + 1) & 1);
                CP_COMMIT();
                const uint32_t slot = (uint32_t)(c & 1);
                const uint2* ap = reinterpret_cast<const uint2*>(
                    smem + SM_A + slot * STAGE_A_BYTES);
                const uint2* bp = reinterpret_cast<const uint2*>(
                    smem + SM_B + slot * STAGE_B_BYTES);
                const int arow = tr * 8, brow = tc * 4;
#pragma unroll 4
                for (int k8 = 0; k8 < BK / 8; k8++) {
                    uint2 av[8], bv[4];
#pragma unroll
                    for (int i = 0; i < 8; i++)
                        av[i] = ap[(arow + i) * (SSTRB / 8) + k8];
#pragma unroll
                    for (int j = 0; j < 4; j++)
                        bv[j] = bp[(brow + j) * (SSTRB / 8) + k8];
#pragma unroll
                    for (int i = 0; i < 8; i++)
#pragma unroll
                        for (int j = 0; j < 4; j++) {
                            acc[i][j] = __dp4a((int)av[i].x, (int)bv[j].x,
                                               acc[i][j]);
                            acc[i][j] = __dp4a((int)av[i].y, (int)bv[j].y,
                                               acc[i][j]);
                        }
                }
            }
            // Epilogue (thread-tile layout).
            const float twoInv = 2.0f * INV_Q2;
#pragma unroll
            for (int i = 0; i < 8; i++) {
                const int iloc = tr * 8 + i;
                const int gi = rowBase + iloc;
                const float sqi = sqA[iloc];
                const int li = labA[iloc];
#pragma unroll
                for (int j = 0; j < 4; j++) {
                    const int jloc = tc * 4 + j;
                    const int gj = colBase + jloc;
                    float w = 2.0f;
                    if (straddle)
                        w = (gi > gj) ? 0.0f : ((gi == gj) ? 1.0f : 2.0f);
                    if (w != 0.0f) {
                        float D = sqi + sqB[jloc] - twoInv * (float)acc[i][j];
                        D = fmaxf(D, 0.0f);
                        if (li == labB[jloc]) {
                            s1 += w * D;
                            cnt += (unsigned int)w;
                        } else {
                            s2 += w * fmaxf(0.0f, margin - D);
                        }
                    }
                }
            }
        }
    }

    // One block reduction + atomics per CTA (both roles).
#pragma unroll
    for (int o = 16; o > 0; o >>= 1) {
        s1 += __shfl_down_sync(0xffffffffu, s1, o);
        s2 += __shfl_down_sync(0xffffffffu, s2, o);
        cnt += __shfl_down_sync(0xffffffffu, cnt, o);
    }
    float* r1 = reinterpret_cast<float*>(smem + SM_RED);
    float* r2 = r1 + 8;
    unsigned int* rc = reinterpret_cast<unsigned int*>(r2 + 8);
    __syncthreads();
    if (lane == 0) {
        r1[wid] = s1;
        r2[wid] = s2;
        rc[wid] = cnt;
    }
    __syncthreads();
    if (tid == 0) {
        double t1 = 0.0, t2 = 0.0;
        unsigned int tc2 = 0;
#pragma unroll
        for (int w = 0; w < 8; w++) {
            t1 += (double)r1[w];
            t2 += (double)r2[w];
            tc2 += rc[w];
        }
        atomicAdd(&g_sum1, t1);
        atomicAdd(&g_sum2, t2);
        atomicAdd(&g_cnt, (unsigned long long)tc2);

        __threadfence();
        unsigned int old = atomicAdd(&g_done, 1u);
        if (old == gridDim.x - 1) {
            double zn1 = (double)atomicAdd(&g_cnt, 0ull);
            double t1f = atomicAdd(&g_sum1, 0.0);
            double t2f = atomicAdd(&g_sum2, 0.0);
            double zn2 = (double)n * (double)n - zn1;
            out[0] = (float)(0.5 * (t1f / zn1 + t2f / zn2));
            g_done = 0u;
        }
    }
}

extern "C" void kernel_launch(void* const* d_in, const int* in_sizes, int n_in,
                              void* d_out, int out_size) {
    const float* X = (const float*)d_in[0];
    const int* lab = (const int*)d_in[1];
    const float* marginp = (const float*)d_in[2];
    float* out = (float*)d_out;

    int n = in_sizes[1];
    int d = in_sizes[0] / n;

    cudaFuncSetAttribute(pair_kernel,
                         cudaFuncAttributeMaxDynamicSharedMemorySize, SMEM_TOTAL);

    convert_kernel<<<(n + 3) / 4, 128>>>(X, n, d);

    int ntm = n / BM;                       // 32
    int ntn = n / BN;                       // 64
    int nb = ntm * ntn - ntm * (ntm - 1);   // 1056 tiles of 128x64
    int ctas = 444;                         // 3 persistent CTAs per SM
    if (ctas > nb) ctas = nb;
    pair_kernel<<<ctas, NTHREADS, SMEM_TOTAL>>>(lab, marginp, out, n, d, ntn, nb);
}